// round 1
// baseline (speedup 1.0000x reference)
#include <cuda_runtime.h>

// Problem constants (fixed by the dataset)
#define IMG    144
#define B_     4
#define N_     1296          // tokens per batch
#define NP_    36
#define JTILES 6
#define JT     216           // N_ / JTILES  (j-tile size)
#define ROWTILES 11          // ceil(1296/128)
#define RT_ROWS 128
#define ATTN_BLOCKS (B_ * ROWTILES * JTILES)   // 264

#define LOG2E 1.4426950408889634f

// Scratch (no allocations allowed): partial sums, layout [b][jt][d(17)][N_]
__device__ float    g_part[B_ * JTILES * 17 * N_];
__device__ unsigned g_maxbits;

// ---------------- packed f32x2 helpers ----------------
__device__ __forceinline__ unsigned long long pack2(float lo, float hi) {
    unsigned long long r;
    asm("mov.b64 %0, {%1, %2};" : "=l"(r) : "f"(lo), "f"(hi));
    return r;
}
__device__ __forceinline__ void unpack2(unsigned long long v, float& lo, float& hi) {
    asm("mov.b64 {%0, %1}, %2;" : "=f"(lo), "=f"(hi) : "l"(v));
}
#define FMA2(d, a, b, c) \
    asm("fma.rn.f32x2 %0, %1, %2, %3;" : "=l"(d) : "l"(a), "l"(b), "l"(c))

// Fast 2^a for a in [-1.5, 3.0]: magic-constant split + deg-5 Taylor for 2^f,
// f in [-0.5, 0.5]. Rel err ~3e-6. Runs entirely on FMA/ALU pipes (no MUFU).
__device__ __forceinline__ float fast_exp2(float a) {
    float fi = a + 12582912.0f;            // 1.5 * 2^23, round-to-nearest int
    float f  = a - (fi - 12582912.0f);     // f in [-0.5, 0.5]
    float p  = 0.0013333558f;
    p = fmaf(p, f, 0.0096181291f);
    p = fmaf(p, f, 0.0555041087f);
    p = fmaf(p, f, 0.2402265070f);
    p = fmaf(p, f, 0.6931471806f);
    p = fmaf(p, f, 1.0f);
    // (fi_bits << 23) == i << 23 exactly (low 9 bits of 0x4B400000 are 0)
    return __int_as_float(__float_as_int(p) + (__float_as_int(fi) << 23));
}

// ---------------- kernel 0a: reset ----------------
__global__ void k_reset() { g_maxbits = 0u; }

// ---------------- kernel 0b: global max (values are >= 0, uint-bit max valid)
__global__ void k_max(const float* __restrict__ x) {
    int idx = blockIdx.x * 256 + threadIdx.x;              // 81*256 = 20736 float4 exactly
    float4 v = reinterpret_cast<const float4*>(x)[idx];
    float m = fmaxf(fmaxf(v.x, v.y), fmaxf(v.z, v.w));
    #pragma unroll
    for (int o = 16; o > 0; o >>= 1)
        m = fmaxf(m, __shfl_xor_sync(0xFFFFFFFFu, m, o));
    __shared__ float sm[8];
    int warp = threadIdx.x >> 5, lane = threadIdx.x & 31;
    if (lane == 0) sm[warp] = m;
    __syncthreads();
    if (warp == 0) {
        m = sm[lane & 7];
        #pragma unroll
        for (int o = 4; o > 0; o >>= 1)
            m = fmaxf(m, __shfl_xor_sync(0xFFFFFFFFu, m, o));
        if (lane == 0) atomicMax(&g_maxbits, __float_as_uint(m));
    }
}

// ---------------- kernel 1: attention partials over a j-tile ----------------
// Grid: b-major -> rowtile -> jtile. Thread = one query row i. Warp iterates
// over j together -> all shared loads of t_j are broadcasts (conflict-free).
// Scores computed on RAW tokens with scale s = log2e/(16*xmax^2); the q_i
// term is dropped (softmax row-invariant); args bounded so no max pass.
__global__ void __launch_bounds__(128) k_attn(const float* __restrict__ x) {
    __shared__ float s_tok[JT * 16];
    __shared__ float s_cj[JT];

    int bid = blockIdx.x;
    int jt  = bid % JTILES;
    int rt  = (bid / JTILES) % ROWTILES;
    int b   = bid / (JTILES * ROWTILES);
    int tid = threadIdx.x;

    float xmax = __uint_as_float(g_maxbits);
    float s    = LOG2E / (16.0f * xmax * xmax);
    float twoS = 2.0f * s;

    const float* xb = x + b * (N_ * 16);

    // fill tokens for this j-tile (raw, contiguous in memory)
    {
        const float4* src = reinterpret_cast<const float4*>(xb + jt * (JT * 16));
        float4* dst = reinterpret_cast<float4*>(s_tok);
        for (int k = tid; k < JT * 4; k += 128) dst[k] = src[k];
    }
    __syncthreads();
    // per-key constant: c_j = -q_j * s
    for (int jj = tid; jj < JT; jj += 128) {
        const float* r = s_tok + jj * 16;
        float q = 0.f;
        #pragma unroll
        for (int d = 0; d < 16; ++d) q = fmaf(r[d], r[d], q);
        s_cj[jj] = -q * s;
    }
    __syncthreads();

    int i = rt * RT_ROWS + tid;
    if (i >= N_) return;

    // load this thread's query token (raw), pack into f32x2 pairs
    const float4* tiv = reinterpret_cast<const float4*>(xb + i * 16);
    float4 a0 = tiv[0], a1 = tiv[1], a2 = tiv[2], a3 = tiv[3];
    unsigned long long ti[8];
    ti[0] = pack2(a0.x, a0.y); ti[1] = pack2(a0.z, a0.w);
    ti[2] = pack2(a1.x, a1.y); ti[3] = pack2(a1.z, a1.w);
    ti[4] = pack2(a2.x, a2.y); ti[5] = pack2(a2.z, a2.w);
    ti[6] = pack2(a3.x, a3.y); ti[7] = pack2(a3.z, a3.w);

    unsigned long long acc[8];
    #pragma unroll
    for (int k = 0; k < 8; ++k) acc[k] = 0ull;
    float denom = 0.f;

    for (int jj = 0; jj < JT; ++jj) {
        const ulonglong2* rp = reinterpret_cast<const ulonglong2*>(s_tok + jj * 16);
        ulonglong2 p0 = rp[0], p1 = rp[1], p2 = rp[2], p3 = rp[3];

        unsigned long long d2a = 0ull, d2b = 0ull;   // two chains of 4
        FMA2(d2a, ti[0], p0.x, d2a);
        FMA2(d2b, ti[1], p0.y, d2b);
        FMA2(d2a, ti[2], p1.x, d2a);
        FMA2(d2b, ti[3], p1.y, d2b);
        FMA2(d2a, ti[4], p2.x, d2a);
        FMA2(d2b, ti[5], p2.y, d2b);
        FMA2(d2a, ti[6], p3.x, d2a);
        FMA2(d2b, ti[7], p3.y, d2b);
        float la, ha, lb, hb;
        unpack2(d2a, la, ha);
        unpack2(d2b, lb, hb);
        float dot = (la + ha) + (lb + hb);

        float arg = fmaf(dot, twoS, s_cj[jj]);       // in [-1.45, 2.89]
        float w = fast_exp2(arg);
        denom += w;

        unsigned long long w2 = pack2(w, w);
        FMA2(acc[0], w2, p0.x, acc[0]);
        FMA2(acc[1], w2, p0.y, acc[1]);
        FMA2(acc[2], w2, p1.x, acc[2]);
        FMA2(acc[3], w2, p1.y, acc[3]);
        FMA2(acc[4], w2, p2.x, acc[4]);
        FMA2(acc[5], w2, p2.y, acc[5]);
        FMA2(acc[6], w2, p3.x, acc[6]);
        FMA2(acc[7], w2, p3.y, acc[7]);
    }

    // write partials, component-major for coalesced store & later coalesced read
    float* base = g_part + (size_t)((b * JTILES + jt) * 17) * N_;
    #pragma unroll
    for (int k = 0; k < 8; ++k) {
        float lo, hi;
        unpack2(acc[k], lo, hi);
        base[(2 * k) * N_ + i]     = lo;
        base[(2 * k + 1) * N_ + i] = hi;
    }
    base[16 * N_ + i] = denom;
}

// ---------------- kernel 2: combine partials, normalize, fold-permute -------
// img[b, by*4+ky, bx*4+kx] = out[b, by*36+bx, ky*4+kx]; output already in raw
// scale (accumulated raw tokens), so no xmax multiply needed.
__global__ void k_final(float* __restrict__ out) {
    int t = blockIdx.x * blockDim.x + threadIdx.x;
    if (t >= B_ * N_) return;
    int b = t / N_, i = t - b * N_;

    float v[16];
    #pragma unroll
    for (int d = 0; d < 16; ++d) v[d] = 0.f;
    float denom = 0.f;
    #pragma unroll
    for (int jt = 0; jt < JTILES; ++jt) {
        const float* base = g_part + (size_t)((b * JTILES + jt) * 17) * N_;
        #pragma unroll
        for (int d = 0; d < 16; ++d) v[d] += base[d * N_ + i];
        denom += base[16 * N_ + i];
    }
    float r = 1.0f / denom;

    int by = i / NP_, bx = i - by * NP_;
    float* ob = out + b * (IMG * IMG) + (by * 4) * IMG + bx * 4;
    #pragma unroll
    for (int ky = 0; ky < 4; ++ky) {
        float4 o;
        o.x = v[ky * 4 + 0] * r;
        o.y = v[ky * 4 + 1] * r;
        o.z = v[ky * 4 + 2] * r;
        o.w = v[ky * 4 + 3] * r;
        *reinterpret_cast<float4*>(ob + ky * IMG) = o;
    }
}

extern "C" void kernel_launch(void* const* d_in, const int* in_sizes, int n_in,
                              void* d_out, int out_size) {
    const float* x = (const float*)d_in[0];
    float* out = (float*)d_out;

    k_reset<<<1, 1>>>();
    k_max<<<81, 256>>>(x);                       // 81*256*4 = 82944 elements exactly
    k_attn<<<ATTN_BLOCKS, 128>>>(x);
    k_final<<<(B_ * N_ + 127) / 128, 128>>>(out);
}

// round 3
// speedup vs baseline: 1.3253x; 1.3253x over previous
#include <cuda_runtime.h>

// Problem constants (fixed by the dataset)
#define IMG    144
#define B_     4
#define N_     1296          // tokens per batch
#define NP_    36
#define JTILES 6
#define JT     216           // N_ / JTILES  (j-tile size)
#define ROWTILES 11          // ceil(1296/128)
#define RT_ROWS 128
#define ATTN_BLOCKS (B_ * ROWTILES * JTILES)   // 264
#define MAXBLOCKS 81

#define LOG2E 1.4426950408889634f

// Scratch: partial sums, layout [b][jt][d(17)][N_]
__device__ float g_part[B_ * JTILES * 17 * N_];
__device__ float g_bmax[MAXBLOCKS];

// ---------------- packed f32x2 helpers ----------------
__device__ __forceinline__ unsigned long long pack2(float lo, float hi) {
    unsigned long long r;
    asm("mov.b64 %0, {%1, %2};" : "=l"(r) : "f"(lo), "f"(hi));
    return r;
}
__device__ __forceinline__ void unpack2(unsigned long long v, float& lo, float& hi) {
    asm("mov.b64 {%0, %1}, %2;" : "=f"(lo), "=f"(hi) : "l"(v));
}
#define FMA2(d, a, b, c) \
    asm("fma.rn.f32x2 %0, %1, %2, %3;" : "=l"(d) : "l"(a), "l"(b), "l"(c))
#define ADD2(d, a, b) \
    asm("add.rn.f32x2 %0, %1, %2;" : "=l"(d) : "l"(a), "l"(b))

__device__ __forceinline__ float ex2_approx(float a) {
    float r;
    asm("ex2.approx.ftz.f32 %0, %1;" : "=f"(r) : "f"(a));
    return r;
}

// ---------------- kernel 0: per-block max (values >= 0) ----------------
__global__ void k_max(const float* __restrict__ x) {
    int idx = blockIdx.x * 256 + threadIdx.x;              // 81*256 = 20736 float4 exactly
    float4 v = reinterpret_cast<const float4*>(x)[idx];
    float m = fmaxf(fmaxf(v.x, v.y), fmaxf(v.z, v.w));
    #pragma unroll
    for (int o = 16; o > 0; o >>= 1)
        m = fmaxf(m, __shfl_xor_sync(0xFFFFFFFFu, m, o));
    __shared__ float sm[8];
    int warp = threadIdx.x >> 5, lane = threadIdx.x & 31;
    if (lane == 0) sm[warp] = m;
    __syncthreads();
    if (warp == 0) {
        m = sm[lane & 7];
        #pragma unroll
        for (int o = 4; o > 0; o >>= 1)
            m = fmaxf(m, __shfl_xor_sync(0xFFFFFFFFu, m, o));
        if (lane == 0) g_bmax[blockIdx.x] = m;
    }
}

// ---------------- kernel 1: attention partials over a j-tile ----------------
// Thread = one query row i; the whole warp walks j together so every shared
// load of t_j is a broadcast. Scores on RAW tokens, scale s = log2e/(16*xmax^2);
// the q_i term is softmax-invariant and dropped; args bounded -> no max pass.
__global__ void __launch_bounds__(128) k_attn(const float* __restrict__ x) {
    __shared__ float s_tok[JT * 16];
    __shared__ float s_cj[JT];
    __shared__ float s_red[4];

    int bid = blockIdx.x;
    int jt  = bid % JTILES;
    int rt  = (bid / JTILES) % ROWTILES;
    int b   = bid / (JTILES * ROWTILES);
    int tid = threadIdx.x;
    int lane = tid & 31, warp = tid >> 5;

    const float* xb = x + b * (N_ * 16);

    // fill tokens for this j-tile (contiguous in memory)
    {
        const float4* src = reinterpret_cast<const float4*>(xb + jt * (JT * 16));
        float4* dst = reinterpret_cast<float4*>(s_tok);
        for (int k = tid; k < JT * 4; k += 128) dst[k] = src[k];
    }

    // reduce the 81 block maxes (tiny, L2-hit broadcasts)
    float m = (tid < MAXBLOCKS) ? g_bmax[tid] : 0.0f;
    #pragma unroll
    for (int o = 16; o > 0; o >>= 1)
        m = fmaxf(m, __shfl_xor_sync(0xFFFFFFFFu, m, o));
    if (lane == 0) s_red[warp] = m;
    __syncthreads();
    float xmax = fmaxf(fmaxf(s_red[0], s_red[1]), fmaxf(s_red[2], s_red[3]));
    float s    = LOG2E / (16.0f * xmax * xmax);
    float twoS = 2.0f * s;

    // per-key constant: c_j = -q_j * s
    for (int jj = tid; jj < JT; jj += 128) {
        const float* r = s_tok + jj * 16;
        float q = 0.f;
        #pragma unroll
        for (int d = 0; d < 16; ++d) q = fmaf(r[d], r[d], q);
        s_cj[jj] = -q * s;
    }
    __syncthreads();

    int i = rt * RT_ROWS + tid;
    if (i >= N_) return;

    // this thread's query token, packed into f32x2 pairs
    const float4* tiv = reinterpret_cast<const float4*>(xb + i * 16);
    float4 a0 = tiv[0], a1 = tiv[1], a2 = tiv[2], a3 = tiv[3];
    unsigned long long ti[8];
    ti[0] = pack2(a0.x, a0.y); ti[1] = pack2(a0.z, a0.w);
    ti[2] = pack2(a1.x, a1.y); ti[3] = pack2(a1.z, a1.w);
    ti[4] = pack2(a2.x, a2.y); ti[5] = pack2(a2.z, a2.w);
    ti[6] = pack2(a3.x, a3.y); ti[7] = pack2(a3.z, a3.w);

    unsigned long long acc[8];
    #pragma unroll
    for (int k = 0; k < 8; ++k) acc[k] = 0ull;
    unsigned long long accd = 0ull;      // denom duplicated in both halves

    #pragma unroll 4
    for (int jj = 0; jj < JT; ++jj) {
        const ulonglong2* rp = reinterpret_cast<const ulonglong2*>(s_tok + jj * 16);
        ulonglong2 p0 = rp[0], p1 = rp[1], p2 = rp[2], p3 = rp[3];

        unsigned long long d2a = 0ull, d2b = 0ull;   // two chains of 4
        FMA2(d2a, ti[0], p0.x, d2a);
        FMA2(d2b, ti[1], p0.y, d2b);
        FMA2(d2a, ti[2], p1.x, d2a);
        FMA2(d2b, ti[3], p1.y, d2b);
        FMA2(d2a, ti[4], p2.x, d2a);
        FMA2(d2b, ti[5], p2.y, d2b);
        FMA2(d2a, ti[6], p3.x, d2a);
        FMA2(d2b, ti[7], p3.y, d2b);
        ADD2(d2a, d2a, d2b);
        float la, ha;
        unpack2(d2a, la, ha);
        float dot = la + ha;

        float arg = fmaf(dot, twoS, s_cj[jj]);       // in [-1.45, 2.89]
        float w = ex2_approx(arg);                    // MUFU pipe (off FMA)

        unsigned long long w2 = pack2(w, w);
        FMA2(acc[0], w2, p0.x, acc[0]);
        FMA2(acc[1], w2, p0.y, acc[1]);
        FMA2(acc[2], w2, p1.x, acc[2]);
        FMA2(acc[3], w2, p1.y, acc[3]);
        FMA2(acc[4], w2, p2.x, acc[4]);
        FMA2(acc[5], w2, p2.y, acc[5]);
        FMA2(acc[6], w2, p3.x, acc[6]);
        FMA2(acc[7], w2, p3.y, acc[7]);
        unsigned long long one2 = 0x3F8000003F800000ull;  // {1.0f,1.0f}
        FMA2(accd, w2, one2, accd);
    }

    // write partials, component-major: coalesced store & coalesced later read
    float* base = g_part + (size_t)((b * JTILES + jt) * 17) * N_;
    #pragma unroll
    for (int k = 0; k < 8; ++k) {
        float lo, hi;
        unpack2(acc[k], lo, hi);
        base[(2 * k) * N_ + i]     = lo;
        base[(2 * k + 1) * N_ + i] = hi;
    }
    {
        // Both halves of accd hold the SAME full denom (w added to each half
        // every iteration) -> use one half only. (lo+hi would double it.)
        float lo, hi;
        unpack2(accd, lo, hi);
        base[16 * N_ + i] = lo;
    }
}

// ---------------- kernel 2: combine partials, normalize, fold-permute -------
// Load ALL 102 partials first (batched LDGs, high MLP), then reduce. Output is
// accumulated raw tokens so the xmax factor has already cancelled.
__global__ void __launch_bounds__(128, 1) k_final(float* __restrict__ out) {
    int t = blockIdx.x * 128 + threadIdx.x;
    if (t >= B_ * N_) return;
    int b = t / N_, i = t - b * N_;

    const float* p0 = g_part + (size_t)(b * JTILES) * 17 * N_ + i;
    float tmp[JTILES][17];
    #pragma unroll
    for (int jt = 0; jt < JTILES; ++jt) {
        const float* base = p0 + (size_t)jt * 17 * N_;
        #pragma unroll
        for (int d = 0; d < 17; ++d) tmp[jt][d] = base[d * N_];
    }

    float v[17];
    #pragma unroll
    for (int d = 0; d < 17; ++d)
        v[d] = ((tmp[0][d] + tmp[1][d]) + (tmp[2][d] + tmp[3][d]))
             + (tmp[4][d] + tmp[5][d]);

    float r = 1.0f / v[16];

    int by = i / NP_, bx = i - by * NP_;
    float* ob = out + b * (IMG * IMG) + (by * 4) * IMG + bx * 4;
    #pragma unroll
    for (int ky = 0; ky < 4; ++ky) {
        float4 o;
        o.x = v[ky * 4 + 0] * r;
        o.y = v[ky * 4 + 1] * r;
        o.z = v[ky * 4 + 2] * r;
        o.w = v[ky * 4 + 3] * r;
        *reinterpret_cast<float4*>(ob + ky * IMG) = o;
    }
}

extern "C" void kernel_launch(void* const* d_in, const int* in_sizes, int n_in,
                              void* d_out, int out_size) {
    const float* x = (const float*)d_in[0];
    float* out = (float*)d_out;

    k_max<<<MAXBLOCKS, 256>>>(x);                 // 81*256*4 = 82944 elements exactly
    k_attn<<<ATTN_BLOCKS, 128>>>(x);
    k_final<<<(B_ * N_ + 127) / 128, 128>>>(out);
}